// round 3
// baseline (speedup 1.0000x reference)
#include <cuda_runtime.h>
#include <cstdint>

// Problem dims
#define BATCH 64
#define N1    1152
#define PDIM  8
#define N2    128
#define DDIM  16
// derived
#define KX    (N1*PDIM)          // 9216
#define BI    (BATCH*N1)         // 73728
#define EPSF  1.1920929e-7f

typedef unsigned long long ull;

// ---------------- scratch (device globals; no allocations) ----------------
__device__ float g_v0[N2 * BATCH * DDIM];        // [n][b][d]   512 KB
__device__ float g_raw[(size_t)N2 * N1 * BATCH]; // [n][i][b]   37.7 MB
__device__ float g_mx[BI];
__device__ float g_inv[BI];

// ---------------- packed f32x2 helpers ----------------
__device__ __forceinline__ ull ffma2(ull a, ull b, ull c) {
    ull d;
    asm("fma.rn.f32x2 %0, %1, %2, %3;" : "=l"(d) : "l"(a), "l"(b), "l"(c));
    return d;
}
__device__ __forceinline__ ull fmul2(ull a, ull b) {
    ull d;
    asm("mul.rn.f32x2 %0, %1, %2;" : "=l"(d) : "l"(a), "l"(b));
    return d;
}
__device__ __forceinline__ ull pack2(float lo, float hi) {
    ull r;
    asm("mov.b64 %0, {%1, %2};" : "=l"(r) : "f"(lo), "f"(hi));
    return r;
}
__device__ __forceinline__ float hadd2(ull v) {
    float lo, hi;
    asm("mov.b64 {%0, %1}, %2;" : "=f"(lo), "=f"(hi) : "l"(v));
    return lo + hi;
}

// ---------------- shared-tile loaders (common pattern) ----------------
// ws: [16 il][128] floats (W[i0+il, n, d, p], linear d*8+p)
// xs: [64 b][132] floats (x[b, i0+il, p] at b*132 + il*8 + p; pad 132 kills bank conflicts)
__device__ __forceinline__ void load_tiles(float* ws, float* xs,
                                           const float* __restrict__ x,
                                           const float* __restrict__ W,
                                           int n, int i0, int t) {
#pragma unroll
    for (int k = 0; k < 2; k++) {          // 512 float4 of W
        int f4 = t + k * 256;
        int il = f4 >> 5, c4 = f4 & 31;
        reinterpret_cast<float4*>(ws)[il * 32 + c4] =
            *reinterpret_cast<const float4*>(W + (size_t)(i0 + il) * (N2 * DDIM * PDIM)
                                               + (size_t)n * (DDIM * PDIM) + c4 * 4);
    }
#pragma unroll
    for (int k = 0; k < 8; k++) {          // 2048 float4 of x
        int f4 = t + k * 256;
        int bb = f4 >> 5, r4 = f4 & 31;
        *reinterpret_cast<float4*>(&xs[bb * 132 + r4 * 4]) =
            *reinterpret_cast<const float4*>(x + (size_t)bb * KX + i0 * PDIM + r4 * 4);
    }
}

// =====================================================================
// K1: v0[n][b][d] = squash( (1/128) * sum_{i,p} W[i,n,d,p] x[b,i,p] )
// =====================================================================
__global__ void __launch_bounds__(256) cap_k1(const float* __restrict__ x,
                                              const float* __restrict__ W) {
    __shared__ float ws[16 * 128];
    __shared__ float xs[64 * 132];
    const int n = blockIdx.x;
    const int t = threadIdx.x;
    const int b0 = t & 31;
    const int q  = t >> 5;         // 0..7
    const int b1 = b0 + 32;

    ull accA[16], accB[16];
#pragma unroll
    for (int d = 0; d < 16; d++) { accA[d] = 0ULL; accB[d] = 0ULL; }

    for (int i0 = 0; i0 < N1; i0 += 16) {
        __syncthreads();
        load_tiles(ws, xs, x, W, n, i0, t);
        __syncthreads();
#pragma unroll
        for (int k = 0; k < 2; k++) {
            const int il = q * 2 + k;
            const ulonglong2* wv =
                reinterpret_cast<const ulonglong2*>(&ws[il * 128]);
            ulonglong2 xA01 = *reinterpret_cast<const ulonglong2*>(&xs[b0 * 132 + il * 8]);
            ulonglong2 xA23 = *reinterpret_cast<const ulonglong2*>(&xs[b0 * 132 + il * 8 + 4]);
            ulonglong2 xB01 = *reinterpret_cast<const ulonglong2*>(&xs[b1 * 132 + il * 8]);
            ulonglong2 xB23 = *reinterpret_cast<const ulonglong2*>(&xs[b1 * 132 + il * 8 + 4]);
#pragma unroll
            for (int d = 0; d < 16; d++) {
                ulonglong2 w01 = wv[d * 2], w23 = wv[d * 2 + 1];
                accA[d] = ffma2(w01.x, xA01.x, accA[d]);
                accA[d] = ffma2(w01.y, xA01.y, accA[d]);
                accA[d] = ffma2(w23.x, xA23.x, accA[d]);
                accA[d] = ffma2(w23.y, xA23.y, accA[d]);
                accB[d] = ffma2(w01.x, xB01.x, accB[d]);
                accB[d] = ffma2(w01.y, xB01.y, accB[d]);
                accB[d] = ffma2(w23.x, xB23.x, accB[d]);
                accB[d] = ffma2(w23.y, xB23.y, accB[d]);
            }
        }
    }
    __syncthreads();
    // reduce the 8 q-partials per b (reuse xs as [64][132] scratch)
#pragma unroll
    for (int d = 0; d < 16; d++) {
        xs[b0 * 132 + q * 16 + d] = hadd2(accA[d]);
        xs[b1 * 132 + q * 16 + d] = hadd2(accB[d]);
    }
    __syncthreads();
    if (t < 64) {
        float s[16];
        float sq = 0.f;
#pragma unroll
        for (int d = 0; d < 16; d++) {
            float v = 0.f;
#pragma unroll
            for (int qq = 0; qq < 8; qq++) v += xs[t * 132 + qq * 16 + d];
            v *= (1.f / 128.f);
            s[d] = v;
            sq += v * v;
        }
        float f = sq / ((1.f + sq) * sqrtf(sq + EPSF));
#pragma unroll
        for (int d = 0; d < 16; d++)
            g_v0[n * (BATCH * DDIM) + t * DDIM + d] = f * s[d];
    }
}

// =====================================================================
// K2: raw[n][i][b] = sum_{d,p} W[i,n,d,p] x[b,i,p] v0[n,b,d]
//     = sum_p x[b,i,p] * ( sum_d v0[n,b,d] W[i,n,d,p] )
// =====================================================================
__global__ void __launch_bounds__(256) cap_k2(const float* __restrict__ x,
                                              const float* __restrict__ W) {
    __shared__ float ws[16 * 128];
    __shared__ float xs[64 * 132];
    __shared__ float v0s[BATCH * DDIM];
    const int n = blockIdx.x;
    const int t = threadIdx.x;
    const int b0 = t & 31;
    const int q  = t >> 5;
    const int b1 = b0 + 32;

    for (int k = t; k < BATCH * DDIM; k += 256)
        v0s[k] = g_v0[n * (BATCH * DDIM) + k];
    __syncthreads();

    ull uA[16], uB[16];
#pragma unroll
    for (int d = 0; d < 16; d++) {
        float vA = v0s[b0 * DDIM + d];
        float vB = v0s[b1 * DDIM + d];
        uA[d] = pack2(vA, vA);
        uB[d] = pack2(vB, vB);
    }

    for (int i0 = 0; i0 < N1; i0 += 16) {
        __syncthreads();
        load_tiles(ws, xs, x, W, n, i0, t);
        __syncthreads();
#pragma unroll
        for (int k = 0; k < 2; k++) {
            const int il = q * 2 + k;
            const int i = i0 + il;
            const ulonglong2* wv =
                reinterpret_cast<const ulonglong2*>(&ws[il * 128]);
            ull tA0 = 0, tA1 = 0, tA2 = 0, tA3 = 0;
            ull tB0 = 0, tB1 = 0, tB2 = 0, tB3 = 0;
#pragma unroll
            for (int d = 0; d < 16; d++) {
                ulonglong2 w01 = wv[d * 2], w23 = wv[d * 2 + 1];
                tA0 = ffma2(uA[d], w01.x, tA0);
                tA1 = ffma2(uA[d], w01.y, tA1);
                tA2 = ffma2(uA[d], w23.x, tA2);
                tA3 = ffma2(uA[d], w23.y, tA3);
                tB0 = ffma2(uB[d], w01.x, tB0);
                tB1 = ffma2(uB[d], w01.y, tB1);
                tB2 = ffma2(uB[d], w23.x, tB2);
                tB3 = ffma2(uB[d], w23.y, tB3);
            }
            ulonglong2 xA01 = *reinterpret_cast<const ulonglong2*>(&xs[b0 * 132 + il * 8]);
            ulonglong2 xA23 = *reinterpret_cast<const ulonglong2*>(&xs[b0 * 132 + il * 8 + 4]);
            ulonglong2 xB01 = *reinterpret_cast<const ulonglong2*>(&xs[b1 * 132 + il * 8]);
            ulonglong2 xB23 = *reinterpret_cast<const ulonglong2*>(&xs[b1 * 132 + il * 8 + 4]);
            ull rA = fmul2(xA01.x, tA0);
            rA = ffma2(xA01.y, tA1, rA);
            rA = ffma2(xA23.x, tA2, rA);
            rA = ffma2(xA23.y, tA3, rA);
            ull rB = fmul2(xB01.x, tB0);
            rB = ffma2(xB01.y, tB1, rB);
            rB = ffma2(xB23.x, tB2, rB);
            rB = ffma2(xB23.y, tB3, rB);
            g_raw[(size_t)n * BI + i * BATCH + b0] = hadd2(rA);
            g_raw[(size_t)n * BI + i * BATCH + b1] = hadd2(rB);
        }
    }
}

// =====================================================================
// K3: per (b,i) softmax stats over n: mx = max_n raw, inv = 1/sum_n exp(raw-mx)
// =====================================================================
__global__ void __launch_bounds__(256) cap_k3() {
    const int j = blockIdx.x * 256 + threadIdx.x;   // j = i*64 + b
    float m = -1e30f;
#pragma unroll 8
    for (int n = 0; n < N2; n++)
        m = fmaxf(m, g_raw[(size_t)n * BI + j]);
    float s = 0.f;
#pragma unroll 8
    for (int n = 0; n < N2; n++)
        s += __expf(g_raw[(size_t)n * BI + j] - m);
    g_mx[j]  = m;
    g_inv[j] = 1.f / s;
}

// =====================================================================
// K4: out[b][n][d] = squash_d( sum_i c[b,i,n] * sum_p W[i,n,d,p] x[b,i,p] )
//     c computed on the fly from raw + stats; c is folded into x per (b,i).
// =====================================================================
__global__ void __launch_bounds__(256) cap_k4(const float* __restrict__ x,
                                              const float* __restrict__ W,
                                              float* __restrict__ out) {
    __shared__ float ws[16 * 128];
    __shared__ float xs[64 * 132];
    const int n = blockIdx.x;
    const int t = threadIdx.x;
    const int b0 = t & 31;
    const int q  = t >> 5;
    const int b1 = b0 + 32;

    ull accA[16], accB[16];
#pragma unroll
    for (int d = 0; d < 16; d++) { accA[d] = 0ULL; accB[d] = 0ULL; }

    for (int i0 = 0; i0 < N1; i0 += 16) {
        __syncthreads();
        load_tiles(ws, xs, x, W, n, i0, t);
        __syncthreads();
#pragma unroll
        for (int k = 0; k < 2; k++) {
            const int il = q * 2 + k;
            const int i = i0 + il;
            const int j0 = i * BATCH + b0;
            const int j1 = i * BATCH + b1;
            float cA = __expf(g_raw[(size_t)n * BI + j0] - g_mx[j0]) * g_inv[j0];
            float cB = __expf(g_raw[(size_t)n * BI + j1] - g_mx[j1]) * g_inv[j1];
            ull c2A = pack2(cA, cA);
            ull c2B = pack2(cB, cB);
            ulonglong2 xA01 = *reinterpret_cast<const ulonglong2*>(&xs[b0 * 132 + il * 8]);
            ulonglong2 xA23 = *reinterpret_cast<const ulonglong2*>(&xs[b0 * 132 + il * 8 + 4]);
            ulonglong2 xB01 = *reinterpret_cast<const ulonglong2*>(&xs[b1 * 132 + il * 8]);
            ulonglong2 xB23 = *reinterpret_cast<const ulonglong2*>(&xs[b1 * 132 + il * 8 + 4]);
            ull xa0 = fmul2(c2A, xA01.x), xa1 = fmul2(c2A, xA01.y);
            ull xa2 = fmul2(c2A, xA23.x), xa3 = fmul2(c2A, xA23.y);
            ull xb0 = fmul2(c2B, xB01.x), xb1 = fmul2(c2B, xB01.y);
            ull xb2 = fmul2(c2B, xB23.x), xb3 = fmul2(c2B, xB23.y);
            const ulonglong2* wv =
                reinterpret_cast<const ulonglong2*>(&ws[il * 128]);
#pragma unroll
            for (int d = 0; d < 16; d++) {
                ulonglong2 w01 = wv[d * 2], w23 = wv[d * 2 + 1];
                accA[d] = ffma2(w01.x, xa0, accA[d]);
                accA[d] = ffma2(w01.y, xa1, accA[d]);
                accA[d] = ffma2(w23.x, xa2, accA[d]);
                accA[d] = ffma2(w23.y, xa3, accA[d]);
                accB[d] = ffma2(w01.x, xb0, accB[d]);
                accB[d] = ffma2(w01.y, xb1, accB[d]);
                accB[d] = ffma2(w23.x, xb2, accB[d]);
                accB[d] = ffma2(w23.y, xb3, accB[d]);
            }
        }
    }
    __syncthreads();
#pragma unroll
    for (int d = 0; d < 16; d++) {
        xs[b0 * 132 + q * 16 + d] = hadd2(accA[d]);
        xs[b1 * 132 + q * 16 + d] = hadd2(accB[d]);
    }
    __syncthreads();
    if (t < 64) {
        float s[16];
        float sq = 0.f;
#pragma unroll
        for (int d = 0; d < 16; d++) {
            float v = 0.f;
#pragma unroll
            for (int qq = 0; qq < 8; qq++) v += xs[t * 132 + qq * 16 + d];
            s[d] = v;
            sq += v * v;
        }
        float f = sq / ((1.f + sq) * sqrtf(sq + EPSF));
#pragma unroll
        for (int d = 0; d < 16; d++)
            out[(size_t)t * (N2 * DDIM) + n * DDIM + d] = f * s[d];
    }
}

// =====================================================================
extern "C" void kernel_launch(void* const* d_in, const int* in_sizes, int n_in,
                              void* d_out, int out_size) {
    const float* x = (const float*)d_in[0];
    const float* W = (const float*)d_in[1];
    // x has 589824 elems, W has 18874368 — guard against metadata ordering surprises
    if (n_in >= 2 && in_sizes[0] > in_sizes[1]) {
        const float* tmp = x; x = W; W = tmp;
    }
    float* out = (float*)d_out;

    cap_k1<<<N2, 256>>>(x, W);
    cap_k2<<<N2, 256>>>(x, W);
    cap_k3<<<BI / 256, 256>>>();
    cap_k4<<<N2, 256>>>(x, W, out);
}

// round 4
// speedup vs baseline: 1.2359x; 1.2359x over previous
#include <cuda_runtime.h>
#include <cstdint>

// Problem dims
#define BATCH 64
#define N1    1152
#define PDIM  8
#define N2    128
#define DDIM  16
// derived
#define KX    (N1*PDIM)          // 9216
#define BI    (BATCH*N1)         // 73728
#define EPSF  1.1920929e-7f

// tiling
#define SLICES 6
#define ISL    (N1/SLICES)       // 192 i's per slice
#define IL     8                 // i's per smem tile
#define TILES  (ISL/IL)          // 24
#define XROW   68                // padded x row (64 + 4)

typedef unsigned long long ull;

// ---------------- scratch (device globals; no allocations) ----------------
__device__ float g_v0[N2 * BATCH * DDIM];              // [n][b][d]
__device__ float g_raw[(size_t)N2 * N1 * BATCH];       // [n][i][b]  37.7 MB
__device__ float g_mx[BI];
__device__ float g_inv[BI];
__device__ float g_part[(size_t)SLICES * N2 * BATCH * DDIM]; // [s][n][b][d] 3 MB

// ---------------- packed f32x2 helpers ----------------
__device__ __forceinline__ ull ffma2(ull a, ull b, ull c) {
    ull d;
    asm("fma.rn.f32x2 %0, %1, %2, %3;" : "=l"(d) : "l"(a), "l"(b), "l"(c));
    return d;
}
__device__ __forceinline__ ull fmul2(ull a, ull b) {
    ull d;
    asm("mul.rn.f32x2 %0, %1, %2;" : "=l"(d) : "l"(a), "l"(b));
    return d;
}
__device__ __forceinline__ ull pack2(float lo, float hi) {
    ull r;
    asm("mov.b64 %0, {%1, %2};" : "=l"(r) : "f"(lo), "f"(hi));
    return r;
}
__device__ __forceinline__ float hadd2(ull v) {
    float lo, hi;
    asm("mov.b64 {%0, %1}, %2;" : "=f"(lo), "=f"(hi) : "l"(v));
    return lo + hi;
}

// ---------------- cp.async helpers ----------------
__device__ __forceinline__ void cpa16(uint32_t s, const float* g) {
    asm volatile("cp.async.cg.shared.global [%0], [%1], 16;" :: "r"(s), "l"(g));
}
__device__ __forceinline__ void cpcommit() {
    asm volatile("cp.async.commit_group;");
}

// ---------------- async tile loader ----------------
// ws tile: [IL=8 il][128] floats = W[i0+il, n, d, p] (linear d*8+p)       4 KB
// xs tile: [64 b][XROW=68] floats, x[b, i0+il, p] at b*68 + il*8 + p    17 KB
__device__ __forceinline__ void tile_load(uint32_t ws_s, uint32_t xs_s,
                                          const float* __restrict__ x,
                                          const float* __restrict__ W,
                                          int n, int i0, int t) {
    {   // W: 256 float4, one per thread
        int il = t >> 5, c4 = t & 31;
        cpa16(ws_s + (uint32_t)(il * 128 + c4 * 4) * 4,
              W + (size_t)(i0 + il) * (N2 * DDIM * PDIM)
                + (size_t)n * (DDIM * PDIM) + c4 * 4);
    }
#pragma unroll
    for (int k = 0; k < 4; k++) {   // x: 1024 float4, 4 per thread
        int f4 = t + k * 256;
        int bb = f4 >> 4, r4 = f4 & 15;
        cpa16(xs_s + (uint32_t)(bb * XROW + r4 * 4) * 4,
              x + (size_t)bb * KX + i0 * PDIM + r4 * 4);
    }
}

// =====================================================================
// K1 partial: part[s][n][b][d] = sum_{i in slice, p} W[i,n,d,p] x[b,i,p]
// 256 thr: warp w (0..7): sub=w>>2 -> b=lane+32*sub; il in {w&3, (w&3)+4}
// =====================================================================
__global__ void __launch_bounds__(256, 3) cap_k1p(const float* __restrict__ x,
                                                  const float* __restrict__ W) {
    __shared__ float ws[2][IL * 128];
    __shared__ float xs[2][BATCH * XROW];
    const int n = blockIdx.x, s = blockIdx.y;
    const int t = threadIdx.x, w = t >> 5, lane = t & 31;
    const int il0 = w & 3;
    const int b = lane + 32 * (w >> 2);
    const int ib = s * ISL;
    uint32_t wss[2] = { (uint32_t)__cvta_generic_to_shared(&ws[0][0]),
                        (uint32_t)__cvta_generic_to_shared(&ws[1][0]) };
    uint32_t xss[2] = { (uint32_t)__cvta_generic_to_shared(&xs[0][0]),
                        (uint32_t)__cvta_generic_to_shared(&xs[1][0]) };

    ull acc[16];
#pragma unroll
    for (int d = 0; d < 16; d++) acc[d] = 0ULL;

    tile_load(wss[0], xss[0], x, W, n, ib, t);
    cpcommit();

    for (int tt = 0; tt < TILES; tt++) {
        if (tt + 1 < TILES) {
            tile_load(wss[(tt + 1) & 1], xss[(tt + 1) & 1], x, W, n,
                      ib + (tt + 1) * IL, t);
            cpcommit();
            asm volatile("cp.async.wait_group 1;");
        } else {
            asm volatile("cp.async.wait_group 0;");
        }
        __syncthreads();
        const float* wsb = ws[tt & 1];
        const float* xsb = xs[tt & 1];
#pragma unroll
        for (int h = 0; h < 2; h++) {
            const int il = il0 + 4 * h;
            ulonglong2 x01 = *(const ulonglong2*)&xsb[b * XROW + il * 8];
            ulonglong2 x23 = *(const ulonglong2*)&xsb[b * XROW + il * 8 + 4];
            const ulonglong2* wv = (const ulonglong2*)&wsb[il * 128];
#pragma unroll
            for (int d = 0; d < 16; d++) {
                ulonglong2 w01 = wv[2 * d], w23 = wv[2 * d + 1];
                acc[d] = ffma2(w01.x, x01.x, acc[d]);
                acc[d] = ffma2(w01.y, x01.y, acc[d]);
                acc[d] = ffma2(w23.x, x23.x, acc[d]);
                acc[d] = ffma2(w23.y, x23.y, acc[d]);
            }
        }
        __syncthreads();
    }

    // cross-warp reduce into xs[0] (free now): red[w][lane][16]
    float* red = &xs[0][0];
#pragma unroll
    for (int d = 0; d < 16; d++)
        red[w * 512 + lane * 16 + d] = hadd2(acc[d]);
    __syncthreads();
    {
        int bb = t >> 2, dq = t & 3;
        int sub2 = bb >> 5, bl = bb & 31;
        float4 v = make_float4(0.f, 0.f, 0.f, 0.f);
#pragma unroll
        for (int k = 0; k < 4; k++) {
            const float* r = &red[(sub2 * 4 + k) * 512 + bl * 16 + dq * 4];
            v.x += r[0]; v.y += r[1]; v.z += r[2]; v.w += r[3];
        }
        *(float4*)&g_part[(((size_t)s * N2 + n) * BATCH + bb) * DDIM + dq * 4] = v;
    }
}

// =====================================================================
// K1 reduce: v0[n][b][d] = squash( (1/128) * sum_s part )
// =====================================================================
__global__ void __launch_bounds__(64) cap_k1r() {
    const int n = blockIdx.x, b = threadIdx.x;
    float sv[16];
#pragma unroll
    for (int d = 0; d < 16; d++) sv[d] = 0.f;
    for (int sl = 0; sl < SLICES; sl++) {
        const float4* p = (const float4*)&g_part[(((size_t)sl * N2 + n) * BATCH + b) * DDIM];
#pragma unroll
        for (int q = 0; q < 4; q++) {
            float4 v = p[q];
            sv[4 * q + 0] += v.x; sv[4 * q + 1] += v.y;
            sv[4 * q + 2] += v.z; sv[4 * q + 3] += v.w;
        }
    }
    float sq = 0.f;
#pragma unroll
    for (int d = 0; d < 16; d++) { sv[d] *= (1.f / 128.f); sq += sv[d] * sv[d]; }
    float f = sq / ((1.f + sq) * sqrtf(sq + EPSF));
    float4* o = (float4*)&g_v0[((size_t)n * BATCH + b) * DDIM];
#pragma unroll
    for (int q = 0; q < 4; q++)
        o[q] = make_float4(f * sv[4 * q], f * sv[4 * q + 1],
                           f * sv[4 * q + 2], f * sv[4 * q + 3]);
}

// =====================================================================
// K2: raw[n][i][b] = sum_p x[b,i,p] * ( sum_d v0[n,b,d] W[i,n,d,p] )
// =====================================================================
__global__ void __launch_bounds__(256, 3) cap_k2(const float* __restrict__ x,
                                                 const float* __restrict__ W) {
    __shared__ float ws[2][IL * 128];
    __shared__ float xs[2][BATCH * XROW];
    const int n = blockIdx.x, s = blockIdx.y;
    const int t = threadIdx.x, w = t >> 5, lane = t & 31;
    const int il0 = w & 3;
    const int b = lane + 32 * (w >> 2);
    const int ib = s * ISL;
    uint32_t wss[2] = { (uint32_t)__cvta_generic_to_shared(&ws[0][0]),
                        (uint32_t)__cvta_generic_to_shared(&ws[1][0]) };
    uint32_t xss[2] = { (uint32_t)__cvta_generic_to_shared(&xs[0][0]),
                        (uint32_t)__cvta_generic_to_shared(&xs[1][0]) };

    ull u[16];
    {
        const float* v0p = &g_v0[((size_t)n * BATCH + b) * DDIM];
#pragma unroll
        for (int q = 0; q < 4; q++) {
            float4 vv = *(const float4*)&v0p[q * 4];
            u[q * 4 + 0] = pack2(vv.x, vv.x);
            u[q * 4 + 1] = pack2(vv.y, vv.y);
            u[q * 4 + 2] = pack2(vv.z, vv.z);
            u[q * 4 + 3] = pack2(vv.w, vv.w);
        }
    }

    tile_load(wss[0], xss[0], x, W, n, ib, t);
    cpcommit();

    for (int tt = 0; tt < TILES; tt++) {
        if (tt + 1 < TILES) {
            tile_load(wss[(tt + 1) & 1], xss[(tt + 1) & 1], x, W, n,
                      ib + (tt + 1) * IL, t);
            cpcommit();
            asm volatile("cp.async.wait_group 1;");
        } else {
            asm volatile("cp.async.wait_group 0;");
        }
        __syncthreads();
        const float* wsb = ws[tt & 1];
        const float* xsb = xs[tt & 1];
        const int i0 = ib + tt * IL;
#pragma unroll
        for (int h = 0; h < 2; h++) {
            const int il = il0 + 4 * h;
            const int i = i0 + il;
            const ulonglong2* wv = (const ulonglong2*)&wsb[il * 128];
            ull t0 = 0, t1 = 0, t2 = 0, t3 = 0;
#pragma unroll
            for (int d = 0; d < 16; d++) {
                ulonglong2 w01 = wv[2 * d], w23 = wv[2 * d + 1];
                t0 = ffma2(u[d], w01.x, t0);
                t1 = ffma2(u[d], w01.y, t1);
                t2 = ffma2(u[d], w23.x, t2);
                t3 = ffma2(u[d], w23.y, t3);
            }
            ulonglong2 x01 = *(const ulonglong2*)&xsb[b * XROW + il * 8];
            ulonglong2 x23 = *(const ulonglong2*)&xsb[b * XROW + il * 8 + 4];
            ull r = fmul2(x01.x, t0);
            r = ffma2(x01.y, t1, r);
            r = ffma2(x23.x, t2, r);
            r = ffma2(x23.y, t3, r);
            g_raw[(size_t)n * BI + (size_t)i * BATCH + b] = hadd2(r);
        }
        __syncthreads();
    }
}

// =====================================================================
// K3: per (b,i) softmax stats over n
// =====================================================================
__global__ void __launch_bounds__(256) cap_k3() {
    const int j = blockIdx.x * 256 + threadIdx.x;   // j = i*64 + b
    float m = -1e30f;
#pragma unroll 8
    for (int n = 0; n < N2; n++)
        m = fmaxf(m, g_raw[(size_t)n * BI + j]);
    float s = 0.f;
#pragma unroll 8
    for (int n = 0; n < N2; n++)
        s += __expf(g_raw[(size_t)n * BI + j] - m);
    g_mx[j]  = m;
    g_inv[j] = 1.f / s;
}

// =====================================================================
// K4 partial: part[s][n][b][d] = sum_{i in slice} c[b,i,n] * pred[b,i,n,d]
// =====================================================================
__global__ void __launch_bounds__(256, 3) cap_k4p(const float* __restrict__ x,
                                                  const float* __restrict__ W) {
    __shared__ float ws[2][IL * 128];
    __shared__ float xs[2][BATCH * XROW];
    const int n = blockIdx.x, s = blockIdx.y;
    const int t = threadIdx.x, w = t >> 5, lane = t & 31;
    const int il0 = w & 3;
    const int b = lane + 32 * (w >> 2);
    const int ib = s * ISL;
    uint32_t wss[2] = { (uint32_t)__cvta_generic_to_shared(&ws[0][0]),
                        (uint32_t)__cvta_generic_to_shared(&ws[1][0]) };
    uint32_t xss[2] = { (uint32_t)__cvta_generic_to_shared(&xs[0][0]),
                        (uint32_t)__cvta_generic_to_shared(&xs[1][0]) };

    ull acc[16];
#pragma unroll
    for (int d = 0; d < 16; d++) acc[d] = 0ULL;

    tile_load(wss[0], xss[0], x, W, n, ib, t);
    cpcommit();

    for (int tt = 0; tt < TILES; tt++) {
        if (tt + 1 < TILES) {
            tile_load(wss[(tt + 1) & 1], xss[(tt + 1) & 1], x, W, n,
                      ib + (tt + 1) * IL, t);
            cpcommit();
            asm volatile("cp.async.wait_group 1;");
        } else {
            asm volatile("cp.async.wait_group 0;");
        }
        __syncthreads();
        const float* wsb = ws[tt & 1];
        const float* xsb = xs[tt & 1];
        const int i0 = ib + tt * IL;
#pragma unroll
        for (int h = 0; h < 2; h++) {
            const int il = il0 + 4 * h;
            const int i = i0 + il;
            const int j = i * BATCH + b;
            float c = __expf(g_raw[(size_t)n * BI + j] - g_mx[j]) * g_inv[j];
            ull c2 = pack2(c, c);
            ulonglong2 x01 = *(const ulonglong2*)&xsb[b * XROW + il * 8];
            ulonglong2 x23 = *(const ulonglong2*)&xsb[b * XROW + il * 8 + 4];
            ull xa0 = fmul2(c2, x01.x), xa1 = fmul2(c2, x01.y);
            ull xa2 = fmul2(c2, x23.x), xa3 = fmul2(c2, x23.y);
            const ulonglong2* wv = (const ulonglong2*)&wsb[il * 128];
#pragma unroll
            for (int d = 0; d < 16; d++) {
                ulonglong2 w01 = wv[2 * d], w23 = wv[2 * d + 1];
                acc[d] = ffma2(w01.x, xa0, acc[d]);
                acc[d] = ffma2(w01.y, xa1, acc[d]);
                acc[d] = ffma2(w23.x, xa2, acc[d]);
                acc[d] = ffma2(w23.y, xa3, acc[d]);
            }
        }
        __syncthreads();
    }

    float* red = &xs[0][0];
#pragma unroll
    for (int d = 0; d < 16; d++)
        red[w * 512 + lane * 16 + d] = hadd2(acc[d]);
    __syncthreads();
    {
        int bb = t >> 2, dq = t & 3;
        int sub2 = bb >> 5, bl = bb & 31;
        float4 v = make_float4(0.f, 0.f, 0.f, 0.f);
#pragma unroll
        for (int k = 0; k < 4; k++) {
            const float* r = &red[(sub2 * 4 + k) * 512 + bl * 16 + dq * 4];
            v.x += r[0]; v.y += r[1]; v.z += r[2]; v.w += r[3];
        }
        *(float4*)&g_part[(((size_t)s * N2 + n) * BATCH + bb) * DDIM + dq * 4] = v;
    }
}

// =====================================================================
// K4 reduce: out[b][n][d] = squash_d( sum_s part[s][n][b][d] )
// =====================================================================
__global__ void __launch_bounds__(64) cap_k4r(float* __restrict__ out) {
    const int n = blockIdx.x, b = threadIdx.x;
    float sv[16];
#pragma unroll
    for (int d = 0; d < 16; d++) sv[d] = 0.f;
    for (int sl = 0; sl < SLICES; sl++) {
        const float4* p = (const float4*)&g_part[(((size_t)sl * N2 + n) * BATCH + b) * DDIM];
#pragma unroll
        for (int q = 0; q < 4; q++) {
            float4 v = p[q];
            sv[4 * q + 0] += v.x; sv[4 * q + 1] += v.y;
            sv[4 * q + 2] += v.z; sv[4 * q + 3] += v.w;
        }
    }
    float sq = 0.f;
#pragma unroll
    for (int d = 0; d < 16; d++) sq += sv[d] * sv[d];
    float f = sq / ((1.f + sq) * sqrtf(sq + EPSF));
    float4* o = (float4*)&out[((size_t)b * N2 + n) * DDIM];
#pragma unroll
    for (int q = 0; q < 4; q++)
        o[q] = make_float4(f * sv[4 * q], f * sv[4 * q + 1],
                           f * sv[4 * q + 2], f * sv[4 * q + 3]);
}

// =====================================================================
extern "C" void kernel_launch(void* const* d_in, const int* in_sizes, int n_in,
                              void* d_out, int out_size) {
    const float* x = (const float*)d_in[0];
    const float* W = (const float*)d_in[1];
    if (n_in >= 2 && in_sizes[0] > in_sizes[1]) {
        const float* tmp = x; x = W; W = tmp;
    }
    float* out = (float*)d_out;

    dim3 g(N2, SLICES);
    cap_k1p<<<g, 256>>>(x, W);
    cap_k1r<<<N2, 64>>>();
    cap_k2 <<<g, 256>>>(x, W);
    cap_k3 <<<BI / 256, 256>>>();
    cap_k4p<<<g, 256>>>(x, W);
    cap_k4r<<<N2, 64>>>(out);
}